// round 12
// baseline (speedup 1.0000x reference)
#include <cuda_runtime.h>
#include <cstdint>
#include <cstddef>

#define B_      64
#define S_      784
#define SP_     792      // padded synapse rows (sentinel oh=0)
#define T_      500
#define N_      512
#define TP_     522
#define KS_     21
#define THETA_  40
#define CAP_    128
#define NT_     32
#define TC_     128      // tau chunk
#define NCHUNK_ 4
#define THREADS_ 1024
#define GRID_   148
#define PSTR_   544      // u16 pot row stride
#define ZP_     129      // z row stride (u32), odd -> conflict-free
#define NTICK_  (B_ * (N_ / NT_))     // 1024

__device__ int            g_cnt[B_ * T_];
__device__ unsigned short g_list[B_ * T_ * CAP_];   // sentinel-filled (s=784)
__device__ unsigned       g_key[B_ * TP_];
__device__ unsigned       g_oh[S_ * N_];            // one-hot nibble words (v-1 encoding)
__device__ unsigned       g_ticket;

__device__ __forceinline__ int dp4a_(unsigned a, unsigned b, int c) {
    int r;
    asm("dp4a.u32.u32 %0, %1, %2, %3;" : "=r"(r) : "r"(a), "r"(b), "r"(c));
    return r;
}

// ---------------------------------------------------------------------------
__global__ void fill_kernel() {
    int i = blockIdx.x * blockDim.x + threadIdx.x;
    const int L4 = B_ * T_ * CAP_ / 8;
    if (i < L4) {
        uint4 v; v.x = v.y = v.z = v.w = 0x03100310u;
        ((uint4*)g_list)[i] = v;
    }
    if (i < B_ * T_)  g_cnt[i] = 0;
    if (i < B_ * TP_) g_key[i] = 0u;
    if (i == 0)       g_ticket = 0u;
}

// One-hot weights, value-0 dropped: g_oh[s*N+n] = w ? 1<<(4*(w-1)) : 0.
__global__ void oh_kernel(const int* __restrict__ weight) {
    int i = blockIdx.x * blockDim.x + threadIdx.x;
    if (i >= N_ * S_) return;
    int n = i / S_, s = i - n * S_;
    int w = weight[i] & 7;
    g_oh[s * N_ + n] = w ? (1u << (4 * (w - 1))) : 0u;
}

__global__ void prepass_kernel(const float4* __restrict__ x) {
    const int T4 = T_ / 4;
    int idx = blockIdx.x * blockDim.x + threadIdx.x;
    if (idx >= B_ * S_ * T4) return;
    float4 v = x[idx];
    int t4 = idx % T4;
    int bs = idx / T4;
    int s  = bs % S_;
    int b  = bs / S_;
    int tb = t4 * 4;
    if (v.x != 0.0f) { int c = atomicAdd(&g_cnt[b * T_ + tb + 0], 1); if (c < CAP_) g_list[(b * T_ + tb + 0) * CAP_ + c] = (unsigned short)s; }
    if (v.y != 0.0f) { int c = atomicAdd(&g_cnt[b * T_ + tb + 1], 1); if (c < CAP_) g_list[(b * T_ + tb + 1) * CAP_ + c] = (unsigned short)s; }
    if (v.z != 0.0f) { int c = atomicAdd(&g_cnt[b * T_ + tb + 2], 1); if (c < CAP_) g_list[(b * T_ + tb + 2) * CAP_ + c] = (unsigned short)s; }
    if (v.w != 0.0f) { int c = atomicAdd(&g_cnt[b * T_ + tb + 3], 1); if (c < CAP_) g_list[(b * T_ + tb + 3) * CAP_ + c] = (unsigned short)s; }
}

// ---------------------------------------------------------------------------
// smem layout (bytes)
#define OFF_OH   0                      // u32 [SP_][32] one-hot tile             101376
#define OFF_POT  101376                 // u16 [NT_][PSTR_]                        34816
#define OFF_Z    136192                 // u32 [2 buf][2 (L,H)][NT_][ZP_]          66048
#define ZBUF_    (2 * NT_ * ZP_)        // u32 per buffer (L+H)
#define OFF_CNT  202240                 // i32 [T_]                                 2000
#define OFF_TLH  204240                 // uint2 [KS_]                               168
#define OFF_TK   204408                 // u32 ticket                                  8
#define SMEM_TOTAL 204416

__global__ void __launch_bounds__(THREADS_, 1) pot_kernel(const int* __restrict__ table) {
    extern __shared__ unsigned char smem[];
    unsigned*       oh     = (unsigned*)(smem + OFF_OH);
    unsigned short* pot_sm = (unsigned short*)(smem + OFF_POT);
    unsigned*       zbase  = (unsigned*)(smem + OFF_Z);
    int*            cnt_sm = (int*)(smem + OFF_CNT);
    uint2*          TLH    = (uint2*)(smem + OFF_TLH);
    unsigned*       tick   = (unsigned*)(smem + OFF_TK);

    const int tid = threadIdx.x;
    const int warpid = tid >> 5, lane = tid & 31;     // 32 warps
    const int slot = lane >> 3, sub = lane & 7;       // phase-1: tau slot / neuron quad
    const int tl = tid & 31, n2 = tid >> 5;           // phase-2: t group / neuron row

    // Table (time-flipped input): orig[v][j] = table[v][KS_-1-j].
    // v-1 packing: TLH.x bytes = orig[1..4][j], TLH.y bytes = orig[5..7][j],0.
    if (tid < KS_) {
        int j = tid;
        unsigned lo = 0, hi = 0;
#pragma unroll
        for (int v = 1; v <= 4; v++) lo |= ((unsigned)table[v * KS_ + (KS_ - 1 - j)]) << (8 * (v - 1));
#pragma unroll
        for (int v = 5; v <= 7; v++) hi |= ((unsigned)table[v * KS_ + (KS_ - 1 - j)]) << (8 * (v - 5));
        TLH[j] = make_uint2(lo, hi);
    }

    // ---- phase 1: histogram chunk [c0, c0+TCcur) into z buffer
    auto phase1 = [&](int c0, int TCcur, unsigned* zL, unsigned* zH, int b) {
        int ti = (warpid << 2) + slot;
        bool valid = ti < TCcur;                       // whole warp uniform (TCcur mult of 4)
        int cnt_mine = valid ? cnt_sm[c0 + ti] : 0;
        int iters_mine = (cnt_mine + 7) >> 3;
        int iters_min = __reduce_min_sync(0xffffffffu, iters_mine);
        int iters_max = __reduce_max_sync(0xffffffffu, iters_mine);
        const uint4* lp4 = (const uint4*)&g_list[(size_t)(b * T_ + c0 + (valid ? ti : 0)) * CAP_];
        const unsigned* ohb = oh + (sub << 2);
        unsigned zL0 = 0, zL1 = 0, zL2 = 0, zL3 = 0;
        unsigned zH0 = 0, zH1 = 0, zH2 = 0, zH3 = 0;
#define BODY_(it_) do { uint4 v4 = __ldg(lp4 + (it_));                        \
        unsigned za = 0, zb = 0, zc = 0, zd = 0;                              \
        { uint4 o_ = *(const uint4*)(ohb + (v4.x & 0xFFFFu) * 32); za += o_.x; zb += o_.y; zc += o_.z; zd += o_.w; } \
        { uint4 o_ = *(const uint4*)(ohb + (v4.x >> 16)     * 32); za += o_.x; zb += o_.y; zc += o_.z; zd += o_.w; } \
        { uint4 o_ = *(const uint4*)(ohb + (v4.y & 0xFFFFu) * 32); za += o_.x; zb += o_.y; zc += o_.z; zd += o_.w; } \
        { uint4 o_ = *(const uint4*)(ohb + (v4.y >> 16)     * 32); za += o_.x; zb += o_.y; zc += o_.z; zd += o_.w; } \
        { uint4 o_ = *(const uint4*)(ohb + (v4.z & 0xFFFFu) * 32); za += o_.x; zb += o_.y; zc += o_.z; zd += o_.w; } \
        { uint4 o_ = *(const uint4*)(ohb + (v4.z >> 16)     * 32); za += o_.x; zb += o_.y; zc += o_.z; zd += o_.w; } \
        { uint4 o_ = *(const uint4*)(ohb + (v4.w & 0xFFFFu) * 32); za += o_.x; zb += o_.y; zc += o_.z; zd += o_.w; } \
        { uint4 o_ = *(const uint4*)(ohb + (v4.w >> 16)     * 32); za += o_.x; zb += o_.y; zc += o_.z; zd += o_.w; } \
        { unsigned a_ = za & 0x0F0F0F0Fu, b_ = (za >> 4) & 0x0F0F0F0Fu;       \
          zL0 += __byte_perm(a_, b_, 0x5140); zH0 += __byte_perm(a_, b_, 0x7362); } \
        { unsigned a_ = zb & 0x0F0F0F0Fu, b_ = (zb >> 4) & 0x0F0F0F0Fu;       \
          zL1 += __byte_perm(a_, b_, 0x5140); zH1 += __byte_perm(a_, b_, 0x7362); } \
        { unsigned a_ = zc & 0x0F0F0F0Fu, b_ = (zc >> 4) & 0x0F0F0F0Fu;       \
          zL2 += __byte_perm(a_, b_, 0x5140); zH2 += __byte_perm(a_, b_, 0x7362); } \
        { unsigned a_ = zd & 0x0F0F0F0Fu, b_ = (zd >> 4) & 0x0F0F0F0Fu;       \
          zL3 += __byte_perm(a_, b_, 0x5140); zH3 += __byte_perm(a_, b_, 0x7362); } } while (0)
        for (int it = 0; it < iters_min; it++) BODY_(it);           // warp-uniform
        for (int it = iters_min; it < iters_max; it++)              // short diverged tail
            if (it < iters_mine) BODY_(it);
#undef BODY_
        if (valid) {
            int nb = sub << 2;
            zL[(nb + 0) * ZP_ + ti] = zL0; zH[(nb + 0) * ZP_ + ti] = zH0;
            zL[(nb + 1) * ZP_ + ti] = zL1; zH[(nb + 1) * ZP_ + ti] = zH1;
            zL[(nb + 2) * ZP_ + ti] = zL2; zH[(nb + 2) * ZP_ + ti] = zH2;
            zL[(nb + 3) * ZP_ + ti] = zL3; zH[(nb + 3) * ZP_ + ti] = zH3;
        }
    };

    // ---- phase 2: stencil chunk into pot_sm
    auto phase2 = [&](int c0, int TCcur, const unsigned* zL, const unsigned* zH) {
        const unsigned* zLr = zL + n2 * ZP_;
        const unsigned* zHr = zH + n2 * ZP_;
        const int tbase = 1 + 5 * tl;
#define ZLDL(ti_) (((unsigned)(ti_) < (unsigned)TCcur) ? zLr[(ti_)] : 0u)
#define ZLDH(ti_) (((unsigned)(ti_) < (unsigned)TCcur) ? zHr[(ti_)] : 0u)
        int acc0 = 0, acc1 = 0, acc2 = 0, acc3 = 0, acc4 = 0;
        unsigned l0, l1, l2, l3, l4, h0, h1, h2, h3, h4;
        l1 = ZLDL(tbase - 21); h1 = ZLDH(tbase - 21);
        l2 = ZLDL(tbase - 20); h2 = ZLDH(tbase - 20);
        l3 = ZLDL(tbase - 19); h3 = ZLDH(tbase - 19);
        l4 = ZLDL(tbase - 18); h4 = ZLDH(tbase - 18);
#pragma unroll
        for (int jj = 0; jj <= 20; jj++) {
            const int j = 20 - jj;
            l0 = l1; l1 = l2; l2 = l3; l3 = l4;
            h0 = h1; h1 = h2; h2 = h3; h3 = h4;
            l4 = ZLDL(tbase + 3 - j); h4 = ZLDH(tbase + 3 - j);
            uint2 tlh = TLH[j];
            acc0 = dp4a_(l0, tlh.x, acc0); acc0 = dp4a_(h0, tlh.y, acc0);
            acc1 = dp4a_(l1, tlh.x, acc1); acc1 = dp4a_(h1, tlh.y, acc1);
            acc2 = dp4a_(l2, tlh.x, acc2); acc2 = dp4a_(h2, tlh.y, acc2);
            acc3 = dp4a_(l3, tlh.x, acc3); acc3 = dp4a_(h3, tlh.y, acc3);
            acc4 = dp4a_(l4, tlh.x, acc4); acc4 = dp4a_(h4, tlh.y, acc4);
        }
#undef ZLDL
#undef ZLDH
        unsigned short* prow = &pot_sm[n2 * PSTR_ + c0];
        const int lim = TCcur + 20;
        if (tbase     <= lim) prow[tbase    ] = (unsigned short)(prow[tbase    ] + acc0);
        if (tbase + 1 <= lim) prow[tbase + 1] = (unsigned short)(prow[tbase + 1] + acc1);
        if (tbase + 2 <= lim) prow[tbase + 2] = (unsigned short)(prow[tbase + 2] + acc2);
        if (tbase + 3 <= lim) prow[tbase + 3] = (unsigned short)(prow[tbase + 3] + acc3);
        if (tbase + 4 <= lim) prow[tbase + 4] = (unsigned short)(prow[tbase + 4] + acc4);
    };

    int prev_tile = -1;
    for (;;) {
        if (tid == 0) *tick = atomicAdd(&g_ticket, 1u);
        __syncthreads();                              // fences smem reuse
        unsigned my = *tick;
        if (my >= NTICK_) break;
        const int tile = (int)(my >> 6);              // tile-major ordering
        const int b    = (int)(my & 63u);
        const int n0   = tile * NT_;

        // Stage one-hot tile only when the tile changes.
        if (tile != prev_tile) {
            for (int i = tid; i < SP_ * 8; i += THREADS_) {
                int s = i >> 3, q = i & 7;
                uint4 v = make_uint4(0u, 0u, 0u, 0u);
                if (s < S_) v = *(const uint4*)&g_oh[s * N_ + n0 + 4 * q];
                ((uint4*)oh)[i] = v;
            }
            prev_tile = tile;
        }
        for (int i = tid; i < T_; i += THREADS_) {
            int c = g_cnt[b * T_ + i];
            cnt_sm[i] = c < CAP_ ? c : CAP_;
        }
        for (int i = tid; i < NT_ * PSTR_ / 2; i += THREADS_) ((unsigned*)pot_sm)[i] = 0u;
        __syncthreads();

        // Software-pipelined chunks: 1 barrier per chunk.
        {
            unsigned* zL0b = zbase;                       // buffer 0
            unsigned* zH0b = zbase + NT_ * ZP_;
            unsigned* zL1b = zbase + ZBUF_;               // buffer 1
            unsigned* zH1b = zbase + ZBUF_ + NT_ * ZP_;
            phase1(0, TC_, zL0b, zH0b, b);
            __syncthreads();
            for (int k = 0; k < NCHUNK_; k++) {
                int c0 = k * TC_;
                int TCcur = (c0 + TC_ < T_) ? TC_ : (T_ - c0);
                if (k + 1 < NCHUNK_) {
                    int c1 = (k + 1) * TC_;
                    int TCn = (c1 + TC_ < T_) ? TC_ : (T_ - c1);
                    phase1(c1, TCn, (k & 1) ? zL0b : zL1b, (k & 1) ? zH0b : zH1b, b);
                }
                phase2(c0, TCcur, (k & 1) ? zL1b : zL0b, (k & 1) ? zH1b : zH0b);
                __syncthreads();
            }
        }

        // ---- Fused per-(b,t) argmax over this tile -> packed atomicMax.
        for (int t = tid; t < TP_; t += THREADS_) {
            int bv = -1, bn = 0;
#pragma unroll
            for (int nn = 0; nn < NT_; nn++) {
                int v = pot_sm[nn * PSTR_ + t];
                if (v > bv) { bv = v; bn = nn; }
            }
            unsigned key = ((unsigned)bv << 10) | (unsigned)(511 - (n0 + bn));
            atomicMax(&g_key[b * TP_ + t], key);
        }
        __syncthreads();
    }
}

// ---------------------------------------------------------------------------
__global__ void __launch_bounds__(32) scan_kernel(float* __restrict__ out) {
    __shared__ unsigned skey[TP_];
    __shared__ unsigned bm[17];
    int b = blockIdx.x;
    int lane = threadIdx.x;
#pragma unroll
    for (int w = 0; w < 17; w++) {
        int t = w * 32 + lane;
        unsigned key = (t < TP_) ? g_key[b * TP_ + t] : 0u;
        if (t < TP_) skey[t] = key;
        unsigned m = __ballot_sync(0xffffffffu, (int)(key >> 10) > THETA_);
        if (lane == 0) bm[w] = m;
    }
    __syncwarp();
    if (lane == 0) {
        int t = 0;
        while (t < TP_) {
            int w = t >> 5;
            unsigned m = bm[w] & (0xffffffffu << (t & 31));
            while (m == 0u && ++w < 17) m = bm[w];
            if (m == 0u) break;
            int t2 = (w << 5) + __ffs(m) - 1;
            if (t2 >= TP_) break;
            int n = 511 - (int)(skey[t2] & 1023u);
            out[((size_t)b * N_ + n) * TP_ + t2] = 1.0f;
            t = t2 + KS_ + 1;
        }
    }
}

// ---------------------------------------------------------------------------
extern "C" void kernel_launch(void* const* d_in, const int* in_sizes, int n_in,
                              void* d_out, int out_size) {
    const float* x      = (const float*)d_in[0];
    const int*   weight = (const int*)d_in[1];
    const int*   table  = (const int*)d_in[2];
    float*       out    = (float*)d_out;

    cudaFuncSetAttribute(pot_kernel, cudaFuncAttributeMaxDynamicSharedMemorySize, SMEM_TOTAL);

    cudaMemsetAsync(out, 0, (size_t)out_size * sizeof(float), 0);               // 1
    fill_kernel<<<(B_ * T_ * CAP_ / 8 + 255) / 256, 256>>>();                   // 2
    oh_kernel<<<(N_ * S_ + 255) / 256, 256>>>(weight);                          // 3
    prepass_kernel<<<(B_ * S_ * (T_ / 4) + 255) / 256, 256>>>((const float4*)x);// 4

    pot_kernel<<<GRID_, THREADS_, SMEM_TOTAL>>>(table);                         // 5 -> profiled

    scan_kernel<<<B_, 32>>>(out);                                               // 6
}

// round 13
// speedup vs baseline: 1.0200x; 1.0200x over previous
#include <cuda_runtime.h>
#include <cstdint>
#include <cstddef>

#define B_      64
#define S_      784
#define SP_     792      // padded synapse rows (sentinel oh=0)
#define T_      500
#define N_      512
#define TP_     522
#define KS_     21
#define THETA_  40
#define CAP_    128
#define NT_     32
#define TC_     128      // tau chunk
#define NCHUNK_ 4
#define THREADS_ 1024
#define GRID_   148
#define PSTR_   544      // u16 pot row stride
#define ZP_     129      // z row stride (u32), odd -> conflict-free
#define NTICK_  (B_ * (N_ / NT_))     // 1024

__device__ int            g_cnt[B_ * T_];
__device__ unsigned short g_list[B_ * T_ * CAP_];
__device__ unsigned       g_key[B_ * TP_];
__device__ unsigned       g_oh[S_ * N_];            // one-hot nibble words (v-1 encoding)
__device__ unsigned       g_ticket;

__device__ __forceinline__ int dp4a_(unsigned a, unsigned b, int c) {
    int r;
    asm("dp4a.u32.u32 %0, %1, %2, %3;" : "=r"(r) : "r"(a), "r"(b), "r"(c));
    return r;
}

// ---------------------------------------------------------------------------
// Tiny init: zero counters/keys/ticket only (no 128MB list fill).
__global__ void init_kernel() {
    int i = blockIdx.x * blockDim.x + threadIdx.x;
    if (i < B_ * T_)  g_cnt[i] = 0;
    if (i < B_ * TP_) g_key[i] = 0u;
    if (i == 0)       g_ticket = 0u;
}

// One-hot weights, value-0 dropped: g_oh[s*N+n] = w ? 1<<(4*(w-1)) : 0.
__global__ void oh_kernel(const int* __restrict__ weight) {
    int i = blockIdx.x * blockDim.x + threadIdx.x;
    if (i >= N_ * S_) return;
    int n = i / S_, s = i - n * S_;
    int w = weight[i] & 7;
    g_oh[s * N_ + n] = w ? (1u << (4 * (w - 1))) : 0u;
}

__global__ void prepass_kernel(const float4* __restrict__ x) {
    const int T4 = T_ / 4;
    int idx = blockIdx.x * blockDim.x + threadIdx.x;
    if (idx >= B_ * S_ * T4) return;
    float4 v = x[idx];
    int t4 = idx % T4;
    int bs = idx / T4;
    int s  = bs % S_;
    int b  = bs / S_;
    int tb = t4 * 4;
    if (v.x != 0.0f) { int c = atomicAdd(&g_cnt[b * T_ + tb + 0], 1); if (c < CAP_) g_list[(b * T_ + tb + 0) * CAP_ + c] = (unsigned short)s; }
    if (v.y != 0.0f) { int c = atomicAdd(&g_cnt[b * T_ + tb + 1], 1); if (c < CAP_) g_list[(b * T_ + tb + 1) * CAP_ + c] = (unsigned short)s; }
    if (v.z != 0.0f) { int c = atomicAdd(&g_cnt[b * T_ + tb + 2], 1); if (c < CAP_) g_list[(b * T_ + tb + 2) * CAP_ + c] = (unsigned short)s; }
    if (v.w != 0.0f) { int c = atomicAdd(&g_cnt[b * T_ + tb + 3], 1); if (c < CAP_) g_list[(b * T_ + tb + 3) * CAP_ + c] = (unsigned short)s; }
}

// Sentinel-pad each (b,tau) list to the next multiple of 8 (only region read
// by the histogram's 8-spike blocks beyond cnt).
__global__ void pad_kernel() {
    int i = blockIdx.x * blockDim.x + threadIdx.x;
    if (i >= B_ * T_) return;
    int cnt = g_cnt[i];
    cnt = cnt < CAP_ ? cnt : CAP_;
    int end = (cnt + 7) & ~7;
    unsigned short* lp = &g_list[(size_t)i * CAP_];
    for (int c = cnt; c < end; c++) lp[c] = (unsigned short)784;
}

// ---------------------------------------------------------------------------
// smem layout (bytes)
#define OFF_OH   0                      // u32 [SP_][32] one-hot tile             101376
#define OFF_POT  101376                 // u16 [NT_][PSTR_]                        34816
#define OFF_Z    136192                 // u32 [2 (L,H)][NT_][ZP_]                 33024
#define OFF_CNT  169216                 // i32 [T_]                                 2000
#define OFF_TLH  171216                 // uint2 [KS_]                               168
#define OFF_TK   171384                 // u32 ticket                                  8
#define SMEM_TOTAL 171392

__global__ void __launch_bounds__(THREADS_, 1) pot_kernel(const int* __restrict__ table) {
    extern __shared__ unsigned char smem[];
    unsigned*       oh     = (unsigned*)(smem + OFF_OH);
    unsigned short* pot_sm = (unsigned short*)(smem + OFF_POT);
    unsigned*       zL     = (unsigned*)(smem + OFF_Z);
    unsigned*       zH     = (unsigned*)(smem + OFF_Z) + NT_ * ZP_;
    int*            cnt_sm = (int*)(smem + OFF_CNT);
    uint2*          TLH    = (uint2*)(smem + OFF_TLH);
    unsigned*       tick   = (unsigned*)(smem + OFF_TK);

    const int tid = threadIdx.x;
    const int warpid = tid >> 5, lane = tid & 31;     // 32 warps
    const int slot = lane >> 3, sub = lane & 7;       // phase-1: tau slot / neuron quad
    const int tl = tid & 31, n2 = tid >> 5;           // phase-2: t group / neuron row

    // Table (time-flipped input): orig[v][j] = table[v][KS_-1-j].
    // v-1 packing: TLH.x bytes = orig[1..4][j], TLH.y bytes = orig[5..7][j],0.
    if (tid < KS_) {
        int j = tid;
        unsigned lo = 0, hi = 0;
#pragma unroll
        for (int v = 1; v <= 4; v++) lo |= ((unsigned)table[v * KS_ + (KS_ - 1 - j)]) << (8 * (v - 1));
#pragma unroll
        for (int v = 5; v <= 7; v++) hi |= ((unsigned)table[v * KS_ + (KS_ - 1 - j)]) << (8 * (v - 5));
        TLH[j] = make_uint2(lo, hi);
    }

    int prev_tile = -1;
    for (;;) {
        if (tid == 0) *tick = atomicAdd(&g_ticket, 1u);
        __syncthreads();                              // fences smem reuse
        unsigned my = *tick;
        if (my >= NTICK_) break;
        const int tile = (int)(my >> 6);              // tile-major ordering
        const int b    = (int)(my & 63u);
        const int n0   = tile * NT_;

        // Stage one-hot tile only when the tile changes.
        if (tile != prev_tile) {
            for (int i = tid; i < SP_ * 8; i += THREADS_) {
                int s = i >> 3, q = i & 7;
                uint4 v = make_uint4(0u, 0u, 0u, 0u);
                if (s < S_) v = *(const uint4*)&g_oh[s * N_ + n0 + 4 * q];
                ((uint4*)oh)[i] = v;
            }
            prev_tile = tile;
        }
        for (int i = tid; i < T_; i += THREADS_) {
            int c = g_cnt[b * T_ + i];
            cnt_sm[i] = c < CAP_ ? c : CAP_;
        }
        for (int i = tid; i < NT_ * PSTR_ / 2; i += THREADS_) ((unsigned*)pot_sm)[i] = 0u;
        __syncthreads();

        for (int c0 = 0; c0 < T_; c0 += TC_) {
            const int TCcur = (c0 + TC_ < T_) ? TC_ : (T_ - c0);   // 128 or 116

            // ---- Phase 1: warp = 4 taus; lane (slot,sub) serves 4 neurons via
            // one LDS.128 per spike. Exact trip counts: warp-uniform main loop
            // + short predicated tail.
            {
                int ti = (warpid << 2) + slot;
                bool valid = ti < TCcur;               // warp-uniform (TCcur mult of 4)
                int cnt_mine = valid ? cnt_sm[c0 + ti] : 0;
                int iters_mine = (cnt_mine + 7) >> 3;
                int iters_min = __reduce_min_sync(0xffffffffu, iters_mine);
                int iters_max = __reduce_max_sync(0xffffffffu, iters_mine);
                const uint4* lp4 = (const uint4*)&g_list[(size_t)(b * T_ + c0 + (valid ? ti : 0)) * CAP_];
                const unsigned* ohb = oh + (sub << 2);
                unsigned zL0 = 0, zL1 = 0, zL2 = 0, zL3 = 0;
                unsigned zH0 = 0, zH1 = 0, zH2 = 0, zH3 = 0;
#define BODY_(it_) do { uint4 v4 = __ldg(lp4 + (it_));                        \
        unsigned za = 0, zb = 0, zc = 0, zd = 0;                              \
        { uint4 o_ = *(const uint4*)(ohb + (v4.x & 0xFFFFu) * 32); za += o_.x; zb += o_.y; zc += o_.z; zd += o_.w; } \
        { uint4 o_ = *(const uint4*)(ohb + (v4.x >> 16)     * 32); za += o_.x; zb += o_.y; zc += o_.z; zd += o_.w; } \
        { uint4 o_ = *(const uint4*)(ohb + (v4.y & 0xFFFFu) * 32); za += o_.x; zb += o_.y; zc += o_.z; zd += o_.w; } \
        { uint4 o_ = *(const uint4*)(ohb + (v4.y >> 16)     * 32); za += o_.x; zb += o_.y; zc += o_.z; zd += o_.w; } \
        { uint4 o_ = *(const uint4*)(ohb + (v4.z & 0xFFFFu) * 32); za += o_.x; zb += o_.y; zc += o_.z; zd += o_.w; } \
        { uint4 o_ = *(const uint4*)(ohb + (v4.z >> 16)     * 32); za += o_.x; zb += o_.y; zc += o_.z; zd += o_.w; } \
        { uint4 o_ = *(const uint4*)(ohb + (v4.w & 0xFFFFu) * 32); za += o_.x; zb += o_.y; zc += o_.z; zd += o_.w; } \
        { uint4 o_ = *(const uint4*)(ohb + (v4.w >> 16)     * 32); za += o_.x; zb += o_.y; zc += o_.z; zd += o_.w; } \
        { unsigned a_ = za & 0x0F0F0F0Fu, b_ = (za >> 4) & 0x0F0F0F0Fu;       \
          zL0 += __byte_perm(a_, b_, 0x5140); zH0 += __byte_perm(a_, b_, 0x7362); } \
        { unsigned a_ = zb & 0x0F0F0F0Fu, b_ = (zb >> 4) & 0x0F0F0F0Fu;       \
          zL1 += __byte_perm(a_, b_, 0x5140); zH1 += __byte_perm(a_, b_, 0x7362); } \
        { unsigned a_ = zc & 0x0F0F0F0Fu, b_ = (zc >> 4) & 0x0F0F0F0Fu;       \
          zL2 += __byte_perm(a_, b_, 0x5140); zH2 += __byte_perm(a_, b_, 0x7362); } \
        { unsigned a_ = zd & 0x0F0F0F0Fu, b_ = (zd >> 4) & 0x0F0F0F0Fu;       \
          zL3 += __byte_perm(a_, b_, 0x5140); zH3 += __byte_perm(a_, b_, 0x7362); } } while (0)
                for (int it = 0; it < iters_min; it++) BODY_(it);   // warp-uniform
                for (int it = iters_min; it < iters_max; it++)      // short tail
                    if (it < iters_mine) BODY_(it);
#undef BODY_
                if (valid) {
                    int nb = sub << 2;
                    zL[(nb + 0) * ZP_ + ti] = zL0; zH[(nb + 0) * ZP_ + ti] = zH0;
                    zL[(nb + 1) * ZP_ + ti] = zL1; zH[(nb + 1) * ZP_ + ti] = zH1;
                    zL[(nb + 2) * ZP_ + ti] = zL2; zH[(nb + 2) * ZP_ + ti] = zH2;
                    zL[(nb + 3) * ZP_ + ti] = zL3; zH[(nb + 3) * ZP_ + ti] = zH3;
                }
            }
            __syncthreads();

            // ---- Phase 2: 5-wide sliding-window stencil, conflict-free LDS.32.
            {
                const unsigned* zLr = zL + n2 * ZP_;
                const unsigned* zHr = zH + n2 * ZP_;
                const int tbase = 1 + 5 * tl;
#define ZLDL(ti_) (((unsigned)(ti_) < (unsigned)TCcur) ? zLr[(ti_)] : 0u)
#define ZLDH(ti_) (((unsigned)(ti_) < (unsigned)TCcur) ? zHr[(ti_)] : 0u)
                int acc0 = 0, acc1 = 0, acc2 = 0, acc3 = 0, acc4 = 0;
                unsigned l0, l1, l2, l3, l4, h0, h1, h2, h3, h4;
                l1 = ZLDL(tbase - 21); h1 = ZLDH(tbase - 21);
                l2 = ZLDL(tbase - 20); h2 = ZLDH(tbase - 20);
                l3 = ZLDL(tbase - 19); h3 = ZLDH(tbase - 19);
                l4 = ZLDL(tbase - 18); h4 = ZLDH(tbase - 18);
#pragma unroll
                for (int jj = 0; jj <= 20; jj++) {
                    const int j = 20 - jj;
                    l0 = l1; l1 = l2; l2 = l3; l3 = l4;
                    h0 = h1; h1 = h2; h2 = h3; h3 = h4;
                    l4 = ZLDL(tbase + 3 - j); h4 = ZLDH(tbase + 3 - j);
                    uint2 tlh = TLH[j];
                    acc0 = dp4a_(l0, tlh.x, acc0); acc0 = dp4a_(h0, tlh.y, acc0);
                    acc1 = dp4a_(l1, tlh.x, acc1); acc1 = dp4a_(h1, tlh.y, acc1);
                    acc2 = dp4a_(l2, tlh.x, acc2); acc2 = dp4a_(h2, tlh.y, acc2);
                    acc3 = dp4a_(l3, tlh.x, acc3); acc3 = dp4a_(h3, tlh.y, acc3);
                    acc4 = dp4a_(l4, tlh.x, acc4); acc4 = dp4a_(h4, tlh.y, acc4);
                }
#undef ZLDL
#undef ZLDH
                unsigned short* prow = &pot_sm[n2 * PSTR_ + c0];
                const int lim = TCcur + 20;
                if (tbase     <= lim) prow[tbase    ] = (unsigned short)(prow[tbase    ] + acc0);
                if (tbase + 1 <= lim) prow[tbase + 1] = (unsigned short)(prow[tbase + 1] + acc1);
                if (tbase + 2 <= lim) prow[tbase + 2] = (unsigned short)(prow[tbase + 2] + acc2);
                if (tbase + 3 <= lim) prow[tbase + 3] = (unsigned short)(prow[tbase + 3] + acc3);
                if (tbase + 4 <= lim) prow[tbase + 4] = (unsigned short)(prow[tbase + 4] + acc4);
            }
            __syncthreads();
        }

        // ---- Fused per-(b,t) argmax over this tile -> packed atomicMax.
        for (int t = tid; t < TP_; t += THREADS_) {
            int bv = -1, bn = 0;
#pragma unroll
            for (int nn = 0; nn < NT_; nn++) {
                int v = pot_sm[nn * PSTR_ + t];
                if (v > bv) { bv = v; bn = nn; }
            }
            unsigned key = ((unsigned)bv << 10) | (unsigned)(511 - (n0 + bn));
            atomicMax(&g_key[b * TP_ + t], key);
        }
        __syncthreads();
    }
}

// ---------------------------------------------------------------------------
__global__ void __launch_bounds__(32) scan_kernel(float* __restrict__ out) {
    __shared__ unsigned skey[TP_];
    __shared__ unsigned bm[17];
    int b = blockIdx.x;
    int lane = threadIdx.x;
#pragma unroll
    for (int w = 0; w < 17; w++) {
        int t = w * 32 + lane;
        unsigned key = (t < TP_) ? g_key[b * TP_ + t] : 0u;
        if (t < TP_) skey[t] = key;
        unsigned m = __ballot_sync(0xffffffffu, (int)(key >> 10) > THETA_);
        if (lane == 0) bm[w] = m;
    }
    __syncwarp();
    if (lane == 0) {
        int t = 0;
        while (t < TP_) {
            int w = t >> 5;
            unsigned m = bm[w] & (0xffffffffu << (t & 31));
            while (m == 0u && ++w < 17) m = bm[w];
            if (m == 0u) break;
            int t2 = (w << 5) + __ffs(m) - 1;
            if (t2 >= TP_) break;
            int n = 511 - (int)(skey[t2] & 1023u);
            out[((size_t)b * N_ + n) * TP_ + t2] = 1.0f;
            t = t2 + KS_ + 1;
        }
    }
}

// ---------------------------------------------------------------------------
extern "C" void kernel_launch(void* const* d_in, const int* in_sizes, int n_in,
                              void* d_out, int out_size) {
    const float* x      = (const float*)d_in[0];
    const int*   weight = (const int*)d_in[1];
    const int*   table  = (const int*)d_in[2];
    float*       out    = (float*)d_out;

    cudaFuncSetAttribute(pot_kernel, cudaFuncAttributeMaxDynamicSharedMemorySize, SMEM_TOTAL);

    cudaMemsetAsync(out, 0, (size_t)out_size * sizeof(float), 0);               // 1
    init_kernel<<<(B_ * TP_ + 255) / 256, 256>>>();                             // 2
    prepass_kernel<<<(B_ * S_ * (T_ / 4) + 255) / 256, 256>>>((const float4*)x);// 3
    pad_kernel<<<(B_ * T_ + 255) / 256, 256>>>();                               // 4
    // oh_kernel can run before pot; order after pad is fine too.
    oh_kernel<<<(N_ * S_ + 255) / 256, 256>>>(weight);                          // 5... shifted

    pot_kernel<<<GRID_, THREADS_, SMEM_TOTAL>>>(table);                         // 6

    scan_kernel<<<B_, 32>>>(out);                                               // 7
}